// round 1
// baseline (speedup 1.0000x reference)
#include <cuda_runtime.h>
#include <math.h>

#define B_   4
#define C_   2048
#define HW_  196
#define M_   784          // B_*HW_
#define NCLS 80
#define WD   300
#define ID   1024

// ---------------- scratch (static device globals; no allocs) ----------------
__device__ float g_v[ID];                 // fc4_w @ fc3_w
__device__ float g_wordp2[NCLS * ID];     // 2 * (word_features @ fc2_w^T)
__device__ float g_imgp[M_ * ID];         // x @ fc1_w^T
__device__ float g_logits[B_ * NCLS * HW_]; // [b][n][hw], softmaxed in place

// ---------------- f32x2 packed-FMA helpers (sm_100+) ----------------
#define PACK_F32X2(out, lo, hi) \
    asm("mov.b64 %0, {%1, %2};" : "=l"(out) : "r"(__float_as_uint(lo)), "r"(__float_as_uint(hi)))
#define FMA_F32X2(c, a, b) \
    asm("fma.rn.f32x2 %0, %1, %2, %0;" : "+l"(c) : "l"(a), "l"(b))

__device__ __forceinline__ float f2lo(unsigned long long v) { return __uint_as_float((unsigned)v); }
__device__ __forceinline__ float f2hi(unsigned long long v) { return __uint_as_float((unsigned)(v >> 32)); }

// ---------------- K1: v[d] = sum_e fc4_w[e] * fc3_w[e,d] ----------------
// grid 64 blocks x 256 thr; block -> 16 d columns, 16 e-groups of 64
__global__ void k_v(const float* __restrict__ fc3_w, const float* __restrict__ fc4_w) {
    __shared__ float red[256];
    int d0 = blockIdx.x * 16;
    int dl = threadIdx.x & 15;
    int eg = threadIdx.x >> 4;  // 0..15
    int d  = d0 + dl;
    float acc = 0.f;
    int e0 = eg * 64;
#pragma unroll 8
    for (int e = e0; e < e0 + 64; e++)
        acc = fmaf(fc4_w[e], fc3_w[e * ID + d], acc);
    red[threadIdx.x] = acc;
    __syncthreads();
    if (threadIdx.x < 16) {
        float s = 0.f;
#pragma unroll
        for (int g = 0; g < 16; g++) s += red[g * 16 + threadIdx.x];
        g_v[d0 + threadIdx.x] = s;
    }
}

// ---------------- K2: wordp2[n,d] = 2 * sum_k wf[n,k] * fc2_w[d,k] ----------------
// grid 128 blocks x 256 thr; block -> 8 d rows in smem, warp-per-n loop
__global__ void k_wordp(const float* __restrict__ wf, const float* __restrict__ fc2_w) {
    __shared__ float s_fc2[8 * WD];
    int d0 = blockIdx.x * 8;
    for (int e = threadIdx.x; e < 8 * WD; e += 256) {
        int i = e / WD, k = e - i * WD;
        s_fc2[e] = fc2_w[(d0 + i) * WD + k];
    }
    __syncthreads();
    int w = threadIdx.x >> 5, lane = threadIdx.x & 31;
    for (int n = w; n < NCLS; n += 8) {
        float acc[8] = {0, 0, 0, 0, 0, 0, 0, 0};
        const float* wrow = wf + n * WD;
        for (int k = lane; k < WD; k += 32) {
            float wv = wrow[k];
#pragma unroll
            for (int i = 0; i < 8; i++) acc[i] = fmaf(wv, s_fc2[i * WD + k], acc[i]);
        }
#pragma unroll
        for (int i = 0; i < 8; i++) {
#pragma unroll
            for (int off = 16; off; off >>= 1)
                acc[i] += __shfl_xor_sync(~0u, acc[i], off);
        }
        if (lane == 0) {
#pragma unroll
            for (int i = 0; i < 8; i++) g_wordp2[n * ID + d0 + i] = 2.0f * acc[i];
        }
    }
}

// ---------------- K3: imgp[p,d] = sum_c img[b,c,hw] * fc1_w[d,c] ----------------
// 64x64x16 tiles, 256 thr, 4x4 microtile via packed f32x2 FMA, reg-prefetch
__global__ void __launch_bounds__(256) k_gemm(const float* __restrict__ img,
                                              const float* __restrict__ fc1_w) {
    __shared__ __align__(16) float As[16 * 64];
    __shared__ __align__(16) float Bs[16 * 68];
    int tid = threadIdx.x;
    int m0 = blockIdx.y * 64, n0 = blockIdx.x * 64;

    // A-tile loader mapping: p fixed per thread, c varies per k-step
    int pl = tid & 63, cbase = tid >> 6;  // cbase 0..3
    int p  = m0 + pl;
    bool pvalid = p < M_;
    int pb = p / HW_;
    int phw = p - pb * HW_;
    long aBase = (long)pb * (C_ * HW_) + phw;  // + c*HW_
    // B-tile loader mapping
    int bcl = tid & 15, dbase = tid >> 4;  // dbase 0..15
    // compute mapping
    int tx = tid & 15, ty = tid >> 4;

    unsigned long long acc[4][2];
#pragma unroll
    for (int i = 0; i < 4; i++) { acc[i][0] = 0ull; acc[i][1] = 0ull; }

    float aR[4], bR[4];
#pragma unroll
    for (int j = 0; j < 4; j++) {
        int cl = cbase * 4 + j;
        aR[j] = pvalid ? img[aBase + (long)cl * HW_] : 0.0f;
        bR[j] = fc1_w[(n0 + dbase + 16 * j) * C_ + bcl];
    }

    for (int kt = 0; kt < 128; kt++) {
        __syncthreads();
#pragma unroll
        for (int j = 0; j < 4; j++) {
            As[(cbase * 4 + j) * 64 + pl] = aR[j];
            Bs[bcl * 68 + dbase + 16 * j] = bR[j];
        }
        __syncthreads();
        if (kt < 127) {
            int c0 = (kt + 1) * 16;
#pragma unroll
            for (int j = 0; j < 4; j++) {
                int cl = c0 + cbase * 4 + j;
                aR[j] = pvalid ? img[aBase + (long)cl * HW_] : 0.0f;
                bR[j] = fc1_w[(n0 + dbase + 16 * j) * C_ + c0 + bcl];
            }
        }
#pragma unroll
        for (int ck = 0; ck < 16; ck++) {
            float4 av = *(const float4*)(As + ck * 64 + ty * 4);
            float4 bv = *(const float4*)(Bs + ck * 68 + tx * 4);
            unsigned long long b01, b23, a2;
            PACK_F32X2(b01, bv.x, bv.y);
            PACK_F32X2(b23, bv.z, bv.w);
            PACK_F32X2(a2, av.x, av.x);
            FMA_F32X2(acc[0][0], a2, b01); FMA_F32X2(acc[0][1], a2, b23);
            PACK_F32X2(a2, av.y, av.y);
            FMA_F32X2(acc[1][0], a2, b01); FMA_F32X2(acc[1][1], a2, b23);
            PACK_F32X2(a2, av.z, av.z);
            FMA_F32X2(acc[2][0], a2, b01); FMA_F32X2(acc[2][1], a2, b23);
            PACK_F32X2(a2, av.w, av.w);
            FMA_F32X2(acc[3][0], a2, b01); FMA_F32X2(acc[3][1], a2, b23);
        }
    }
#pragma unroll
    for (int i = 0; i < 4; i++) {
        int pi = m0 + ty * 4 + i;
        if (pi < M_) {
            float4 o;
            o.x = f2lo(acc[i][0]); o.y = f2hi(acc[i][0]);
            o.z = f2lo(acc[i][1]); o.w = f2hi(acc[i][1]);
            *(float4*)(g_imgp + (long)pi * ID + n0 + tx * 4) = o;
        }
    }
}

// ---------------- K4: logits[p,n] = sum_d v[d]*tanh(imgp[p,d]*wordp[n,d]) ----------------
// 2 pixels per block (392 blocks); tanh(x) = 1 - 2/(exp(2x)+1), wordp pre-scaled by 2
__global__ void __launch_bounds__(256) k_logits() {
    __shared__ float s_img[2 * ID];
    __shared__ float s_v[ID];
    int p0 = blockIdx.x * 2;
    for (int e = threadIdx.x; e < 2 * ID; e += 256) s_img[e] = g_imgp[(long)p0 * ID + e];
    for (int e = threadIdx.x; e < ID; e += 256) s_v[e] = g_v[e];
    __syncthreads();
    int w = threadIdx.x >> 5, lane = threadIdx.x & 31;
    int b = p0 / HW_;
    int hw0 = p0 - b * HW_;
    for (int n = w; n < NCLS; n += 8) {
        const float* wrow = g_wordp2 + n * ID;
        float a0 = 0.f, a1 = 0.f;
#pragma unroll 4
        for (int d = lane; d < ID; d += 32) {
            float wv = wrow[d];
            float vv = s_v[d];
            float x0 = s_img[d] * wv;
            float x1 = s_img[ID + d] * wv;
            float t0 = 1.0f - __fdividef(2.0f, __expf(x0) + 1.0f);
            float t1 = 1.0f - __fdividef(2.0f, __expf(x1) + 1.0f);
            a0 = fmaf(vv, t0, a0);
            a1 = fmaf(vv, t1, a1);
        }
#pragma unroll
        for (int off = 16; off; off >>= 1) {
            a0 += __shfl_xor_sync(~0u, a0, off);
            a1 += __shfl_xor_sync(~0u, a1, off);
        }
        if (lane == 0) {
            g_logits[(b * NCLS + n) * HW_ + hw0]     = a0;
            g_logits[(b * NCLS + n) * HW_ + hw0 + 1] = a1;
        }
    }
}

// ---------------- K5: softmax over the 196 spatial positions, per (b,n) row ----------------
__global__ void k_softmax() {
    int row = blockIdx.x;
    float* base = g_logits + row * HW_;
    int lane = threadIdx.x;
    float v[7];
    float mx = -1e30f;
#pragma unroll
    for (int i = 0; i < 7; i++) {
        int hw = lane + 32 * i;
        v[i] = (hw < HW_) ? base[hw] : -1e30f;
        mx = fmaxf(mx, v[i]);
    }
#pragma unroll
    for (int off = 16; off; off >>= 1) mx = fmaxf(mx, __shfl_xor_sync(~0u, mx, off));
    float sum = 0.f;
#pragma unroll
    for (int i = 0; i < 7; i++) {
        int hw = lane + 32 * i;
        float e = (hw < HW_) ? __expf(v[i] - mx) : 0.0f;
        v[i] = e;
        sum += e;
    }
#pragma unroll
    for (int off = 16; off; off >>= 1) sum += __shfl_xor_sync(~0u, sum, off);
    float inv = __fdividef(1.0f, sum);
#pragma unroll
    for (int i = 0; i < 7; i++) {
        int hw = lane + 32 * i;
        if (hw < HW_) base[hw] = v[i] * inv;
    }
}

// ---------------- K6: out[b,n,c] = sum_hw coef[b,n,hw] * img[b,c,hw] ----------------
// block = (32-channel tile, batch); img tile + 16-class coef chunk in smem
__global__ void __launch_bounds__(256) k_pool(const float* __restrict__ img,
                                              float* __restrict__ out) {
    __shared__ float s_x[HW_ * 33];     // [hw][c], padded pitch 33 -> conflict-free
    __shared__ float s_c[16 * HW_];     // 16 coef rows
    int b  = blockIdx.y;
    int c0 = blockIdx.x * 32;
    for (int e = threadIdx.x; e < 32 * HW_; e += 256) {
        int cl = e / HW_, hw = e - cl * HW_;
        s_x[hw * 33 + cl] = img[(long)b * C_ * HW_ + (long)(c0 + cl) * HW_ + hw];
    }
    int cl = threadIdx.x & 31, np = threadIdx.x >> 5;
    for (int nc = 0; nc < NCLS; nc += 16) {
        __syncthreads();
        for (int e = threadIdx.x; e < 16 * HW_; e += 256) {
            int i = e / HW_, hw = e - i * HW_;
            s_c[e] = g_logits[(b * NCLS + nc + i) * HW_ + hw];
        }
        __syncthreads();
        const float* cp0 = s_c + (2 * np) * HW_;
        const float* cp1 = cp0 + HW_;
        float acc0 = 0.f, acc1 = 0.f;
#pragma unroll 4
        for (int hw = 0; hw < HW_; hw++) {
            float x = s_x[hw * 33 + cl];
            acc0 = fmaf(x, cp0[hw], acc0);
            acc1 = fmaf(x, cp1[hw], acc1);
        }
        int n = nc + 2 * np;
        out[((long)b * NCLS + n) * C_ + c0 + cl]     = acc0;
        out[((long)b * NCLS + n + 1) * C_ + c0 + cl] = acc1;
    }
}

// ---------------- launch ----------------
extern "C" void kernel_launch(void* const* d_in, const int* in_sizes, int n_in,
                              void* d_out, int out_size) {
    (void)in_sizes; (void)n_in; (void)out_size;
    const float* img  = (const float*)d_in[0];  // [B,C,H,W]
    const float* wf   = (const float*)d_in[1];  // [N,WD]
    const float* fc1w = (const float*)d_in[2];  // [ID,C]
    const float* fc2w = (const float*)d_in[3];  // [ID,WD]
    const float* fc3w = (const float*)d_in[4];  // [ID,ID]
    // d_in[5] fc3_b, d_in[7] fc4_b: constant over softmax axis -> cancel
    const float* fc4w = (const float*)d_in[6];  // [1,ID]
    float* out = (float*)d_out;                 // [B,N,C] fp32

    k_v      <<<64, 256>>>(fc3w, fc4w);
    k_wordp  <<<128, 256>>>(wf, fc2w);
    k_gemm   <<<dim3(16, 13), 256>>>(img, fc1w);
    k_logits <<<392, 256>>>();
    k_softmax<<<320, 32>>>();
    k_pool   <<<dim3(64, 4), 256>>>(img, out);
}

// round 3
// speedup vs baseline: 1.4981x; 1.4981x over previous
#include <cuda_runtime.h>
#include <cuda_bf16.h>
#include <cstdint>

#define B_   4
#define C_   2048
#define HW_  196
#define M_   784          // B_*HW_
#define MPAD 896          // 7*128
#define NCLS 80
#define WD   300
#define ID   1024

// ---------------- scratch (static device globals; no allocs) ----------------
__device__ float g_v[ID];                   // fc4_w @ fc3_w
__device__ float g_wordp[NCLS * ID];        // word_features @ fc2_w^T
__device__ float g_imgp[M_ * ID];           // x @ fc1_w^T
__device__ float g_logits[B_ * NCLS * HW_]; // [b][n][hw], softmaxed in place
// bf16 hi/lo splits, K-major rows of 2048 (16B-aligned for cp.async)
__device__ __align__(16) unsigned short g_ahi[MPAD * C_];
__device__ __align__(16) unsigned short g_alo[MPAD * C_];
__device__ __align__(16) unsigned short g_bhi[ID * C_];
__device__ __align__(16) unsigned short g_blo[ID * C_];

__device__ __forceinline__ uint32_t smem_u32(const void* p) {
    return (uint32_t)__cvta_generic_to_shared(p);
}

// ---------------- K0a: split+transpose img -> a_hi/a_lo [p][c] bf16 ----------------
__global__ void __launch_bounds__(256) k_split_a(const float* __restrict__ img) {
    __shared__ float s[32 * 197];
    int b = blockIdx.y, c0 = blockIdx.x * 32;
    for (int e = threadIdx.x; e < 32 * HW_; e += 256) {
        int ci = e / HW_, hw = e - ci * HW_;
        s[ci * 197 + hw] = img[((long)b * C_ + c0 + ci) * HW_ + hw];
    }
    __syncthreads();
    int ci = threadIdx.x & 31, hw0 = threadIdx.x >> 5;
    for (int hw = hw0; hw < HW_; hw += 8) {
        float x = s[ci * 197 + hw];
        __nv_bfloat16 h = __float2bfloat16_rn(x);
        __nv_bfloat16 l = __float2bfloat16_rn(x - __bfloat162float(h));
        long o = (long)(b * HW_ + hw) * C_ + c0 + ci;
        g_ahi[o] = __bfloat16_as_ushort(h);
        g_alo[o] = __bfloat16_as_ushort(l);
    }
}

// ---------------- K0b: split fc1_w -> b_hi/b_lo [d][c] bf16 ----------------
__global__ void __launch_bounds__(256) k_split_b(const float* __restrict__ w) {
    int idx = blockIdx.x * 256 + threadIdx.x;   // float4 index, ID*C_/4 total
    float4 v = ((const float4*)w)[idx];
    float vv[4] = {v.x, v.y, v.z, v.w};
    unsigned h[4], l[4];
#pragma unroll
    for (int i = 0; i < 4; i++) {
        __nv_bfloat16 hh = __float2bfloat16_rn(vv[i]);
        __nv_bfloat16 ll = __float2bfloat16_rn(vv[i] - __bfloat162float(hh));
        h[i] = __bfloat16_as_ushort(hh);
        l[i] = __bfloat16_as_ushort(ll);
    }
    uint2 H = make_uint2(h[0] | (h[1] << 16), h[2] | (h[3] << 16));
    uint2 L = make_uint2(l[0] | (l[1] << 16), l[2] | (l[3] << 16));
    ((uint2*)g_bhi)[idx] = H;
    ((uint2*)g_blo)[idx] = L;
}

// ---------------- K1: v[d] = sum_e fc4_w[e] * fc3_w[e,d] ----------------
__global__ void k_v(const float* __restrict__ fc3_w, const float* __restrict__ fc4_w) {
    __shared__ float red[256];
    int d0 = blockIdx.x * 16;
    int dl = threadIdx.x & 15;
    int eg = threadIdx.x >> 4;
    int d  = d0 + dl;
    float acc = 0.f;
    int e0 = eg * 64;
#pragma unroll 8
    for (int e = e0; e < e0 + 64; e++)
        acc = fmaf(fc4_w[e], fc3_w[e * ID + d], acc);
    red[threadIdx.x] = acc;
    __syncthreads();
    if (threadIdx.x < 16) {
        float s = 0.f;
#pragma unroll
        for (int g = 0; g < 16; g++) s += red[g * 16 + threadIdx.x];
        g_v[d0 + threadIdx.x] = s;
    }
}

// ---------------- K2: wordp[n,d] = sum_k wf[n,k] * fc2_w[d,k] ----------------
__global__ void k_wordp(const float* __restrict__ wf, const float* __restrict__ fc2_w) {
    __shared__ float s_fc2[8 * WD];
    int d0 = blockIdx.x * 8;
    for (int e = threadIdx.x; e < 8 * WD; e += 256) {
        int i = e / WD, k = e - i * WD;
        s_fc2[e] = fc2_w[(d0 + i) * WD + k];
    }
    __syncthreads();
    int w = threadIdx.x >> 5, lane = threadIdx.x & 31;
    for (int n = w; n < NCLS; n += 8) {
        float acc[8] = {0, 0, 0, 0, 0, 0, 0, 0};
        const float* wrow = wf + n * WD;
        for (int k = lane; k < WD; k += 32) {
            float wv = wrow[k];
#pragma unroll
            for (int i = 0; i < 8; i++) acc[i] = fmaf(wv, s_fc2[i * WD + k], acc[i]);
        }
#pragma unroll
        for (int i = 0; i < 8; i++) {
#pragma unroll
            for (int off = 16; off; off >>= 1)
                acc[i] += __shfl_xor_sync(~0u, acc[i], off);
        }
        if (lane == 0) {
#pragma unroll
            for (int i = 0; i < 8; i++) g_wordp[n * ID + d0 + i] = acc[i];
        }
    }
}

// ---------------- K3: bf16 mma.sync GEMM, 3-term split as K=6144 ----------------
// block 128(M) x 64(N), 8 warps (4x2 of 32x32), K-chunk 32, 4-stage cp.async
#define STAGE_BYTES 12288     // A 128x32x2 = 8192, B 64x32x2 = 4096
#define NCHUNK 192            // 3 terms * 64 chunks

__device__ __forceinline__ void cp16(uint32_t s, const void* g) {
    asm volatile("cp.async.cg.shared.global [%0], [%1], 16;" :: "r"(s), "l"(g));
}
__device__ __forceinline__ void ldm4(uint32_t* r, uint32_t a) {
    asm volatile("ldmatrix.sync.aligned.m8n8.x4.shared.b16 {%0,%1,%2,%3}, [%4];"
                 : "=r"(r[0]), "=r"(r[1]), "=r"(r[2]), "=r"(r[3]) : "r"(a));
}
__device__ __forceinline__ void mma16816(float* c, const uint32_t* a, uint32_t b0, uint32_t b1) {
    asm volatile("mma.sync.aligned.m16n8k16.row.col.f32.bf16.bf16.f32 "
                 "{%0,%1,%2,%3}, {%4,%5,%6,%7}, {%8,%9}, {%0,%1,%2,%3};"
                 : "+f"(c[0]), "+f"(c[1]), "+f"(c[2]), "+f"(c[3])
                 : "r"(a[0]), "r"(a[1]), "r"(a[2]), "r"(a[3]), "r"(b0), "r"(b1));
}

__global__ void __launch_bounds__(256) k_mma() {
    __shared__ __align__(128) char smem[4][STAGE_BYTES];
    uint32_t sbase = smem_u32(smem);
    int tid = threadIdx.x;
    int lane = tid & 31, wid = tid >> 5;
    int warp_m = wid >> 1, warp_n = wid & 1;
    int m0 = blockIdx.y * 128, n0 = blockIdx.x * 64;

    // ---- loader mapping (per thread): A rows ar, ar+64; B row br; 16B chunk c
    int ar = tid >> 2, c = tid & 3;
    uint32_t a_soff  = (uint32_t)(ar * 64 + ((c ^ ((ar >> 1) & 3)) << 4));
    uint32_t a_soff2 = a_soff + 4096;                       // row+64, same swizzle
    uint32_t b_soff  = (uint32_t)(8192 + ar * 64 + ((c ^ ((ar >> 1) & 3)) << 4));
    long a_goff  = (long)(m0 + ar) * C_ + c * 8;
    long a_goff2 = a_goff + (long)64 * C_;
    long b_goff  = (long)(n0 + ar) * C_ + c * 8;

    // ---- ldmatrix address offsets (within stage) per (tile, k-step)
    uint32_t a_loff[2][2], b_loff[2][2];
#pragma unroll
    for (int mt = 0; mt < 2; mt++) {
        int row = warp_m * 32 + mt * 16 + (lane & 15);
        int sel = lane >> 4;
#pragma unroll
        for (int ks = 0; ks < 2; ks++) {
            int ch = 2 * ks + sel;
            a_loff[mt][ks] = (uint32_t)(row * 64 + ((ch ^ ((row >> 1) & 3)) << 4));
        }
    }
#pragma unroll
    for (int bt = 0; bt < 2; bt++) {
        int row = warp_n * 32 + bt * 16 + (lane & 15);
        int sel = lane >> 4;
#pragma unroll
        for (int ks = 0; ks < 2; ks++) {
            int ch = 2 * ks + sel;
            b_loff[bt][ks] = (uint32_t)(8192 + row * 64 + ((ch ^ ((row >> 1) & 3)) << 4));
        }
    }

    float acc[2][4][4];
#pragma unroll
    for (int i = 0; i < 2; i++)
#pragma unroll
        for (int j = 0; j < 4; j++)
#pragma unroll
            for (int q = 0; q < 4; q++) acc[i][j][q] = 0.f;

    // ---- stage loader
    auto load_stage = [&](int ci, int s) {
        int term = ci >> 6;
        long kin = (long)(ci & 63) * 32;
        const unsigned short* Asrc = (term < 2) ? g_ahi : g_alo;
        const unsigned short* Bsrc = (term == 1) ? g_blo : g_bhi;
        uint32_t sa = sbase + (uint32_t)s * STAGE_BYTES;
        cp16(sa + a_soff,  Asrc + a_goff  + kin);
        cp16(sa + a_soff2, Asrc + a_goff2 + kin);
        cp16(sa + b_soff,  Bsrc + b_goff  + kin);
        asm volatile("cp.async.commit_group;" ::: "memory");
    };

    load_stage(0, 0);
    load_stage(1, 1);
    load_stage(2, 2);

    for (int ci = 0; ci < NCHUNK; ci++) {
        asm volatile("cp.async.wait_group 2;" ::: "memory");
        __syncthreads();
        if (ci + 3 < NCHUNK) load_stage(ci + 3, (ci + 3) & 3);
        else asm volatile("cp.async.commit_group;" ::: "memory");

        uint32_t sa = sbase + (uint32_t)(ci & 3) * STAGE_BYTES;
#pragma unroll
        for (int ks = 0; ks < 2; ks++) {
            uint32_t af[2][4], bq[2][4];
            ldm4(af[0], sa + a_loff[0][ks]);
            ldm4(af[1], sa + a_loff[1][ks]);
            ldm4(bq[0], sa + b_loff[0][ks]);
            ldm4(bq[1], sa + b_loff[1][ks]);
#pragma unroll
            for (int mt = 0; mt < 2; mt++) {
                mma16816(acc[mt][0], af[mt], bq[0][0], bq[0][2]);
                mma16816(acc[mt][1], af[mt], bq[0][1], bq[0][3]);
                mma16816(acc[mt][2], af[mt], bq[1][0], bq[1][2]);
                mma16816(acc[mt][3], af[mt], bq[1][1], bq[1][3]);
            }
        }
    }

    // ---- epilogue
#pragma unroll
    for (int mt = 0; mt < 2; mt++) {
#pragma unroll
        for (int nt = 0; nt < 4; nt++) {
            int prow = m0 + warp_m * 32 + mt * 16 + (lane >> 2);
            int ncol = n0 + warp_n * 32 + nt * 8 + (lane & 3) * 2;
            if (prow < M_) {
                float2 v0 = make_float2(acc[mt][nt][0], acc[mt][nt][1]);
                *(float2*)(g_imgp + (long)prow * ID + ncol) = v0;
            }
            if (prow + 8 < M_) {
                float2 v1 = make_float2(acc[mt][nt][2], acc[mt][nt][3]);
                *(float2*)(g_imgp + (long)(prow + 8) * ID + ncol) = v1;
            }
        }
    }
}

// ---------------- K4: logits[p,n] = sum_d v[d]*tanh(imgp[p,d]*wordp[n,d]) ----------------
// 784 blocks: 2 pixels x half the classes each; MUFU tanh.approx
__global__ void __launch_bounds__(256) k_logits() {
    __shared__ float s_img[2 * ID];
    __shared__ float s_v[ID];
    int p0 = (blockIdx.x >> 1) * 2;
    int n0 = (blockIdx.x & 1) * 40;
    for (int e = threadIdx.x; e < 2 * ID; e += 256) s_img[e] = g_imgp[(long)p0 * ID + e];
    for (int e = threadIdx.x; e < ID; e += 256) s_v[e] = g_v[e];
    __syncthreads();
    int w = threadIdx.x >> 5, lane = threadIdx.x & 31;
    int b = p0 / HW_;
    int hw0 = p0 - b * HW_;
    for (int n = n0 + w; n < n0 + 40; n += 8) {
        const float* wrow = g_wordp + n * ID;
        float a0 = 0.f, a1 = 0.f;
#pragma unroll 4
        for (int d = lane; d < ID; d += 32) {
            float wv = wrow[d];
            float vv = s_v[d];
            float x0 = s_img[d] * wv;
            float x1 = s_img[ID + d] * wv;
            float t0, t1;
            asm("tanh.approx.f32 %0, %1;" : "=f"(t0) : "f"(x0));
            asm("tanh.approx.f32 %0, %1;" : "=f"(t1) : "f"(x1));
            a0 = fmaf(vv, t0, a0);
            a1 = fmaf(vv, t1, a1);
        }
#pragma unroll
        for (int off = 16; off; off >>= 1) {
            a0 += __shfl_xor_sync(~0u, a0, off);
            a1 += __shfl_xor_sync(~0u, a1, off);
        }
        if (lane == 0) {
            g_logits[(b * NCLS + n) * HW_ + hw0]     = a0;
            g_logits[(b * NCLS + n) * HW_ + hw0 + 1] = a1;
        }
    }
}

// ---------------- K5: softmax over the 196 spatial positions, per (b,n) row ----------------
__global__ void k_softmax() {
    int row = blockIdx.x;
    float* base = g_logits + row * HW_;
    int lane = threadIdx.x;
    float v[7];
    float mx = -1e30f;
#pragma unroll
    for (int i = 0; i < 7; i++) {
        int hw = lane + 32 * i;
        v[i] = (hw < HW_) ? base[hw] : -1e30f;
        mx = fmaxf(mx, v[i]);
    }
#pragma unroll
    for (int off = 16; off; off >>= 1) mx = fmaxf(mx, __shfl_xor_sync(~0u, mx, off));
    float sum = 0.f;
#pragma unroll
    for (int i = 0; i < 7; i++) {
        int hw = lane + 32 * i;
        float e = (hw < HW_) ? __expf(v[i] - mx) : 0.0f;
        v[i] = e;
        sum += e;
    }
#pragma unroll
    for (int off = 16; off; off >>= 1) sum += __shfl_xor_sync(~0u, sum, off);
    float inv = __fdividef(1.0f, sum);
#pragma unroll
    for (int i = 0; i < 7; i++) {
        int hw = lane + 32 * i;
        if (hw < HW_) base[hw] = v[i] * inv;
    }
}

// ---------------- K6: out[b,n,c] = sum_hw coef[b,n,hw] * img[b,c,hw] ----------------
__global__ void __launch_bounds__(256) k_pool(const float* __restrict__ img,
                                              float* __restrict__ out) {
    __shared__ float s_x[HW_ * 33];
    __shared__ float s_c[16 * HW_];
    int b  = blockIdx.y;
    int c0 = blockIdx.x * 32;
    for (int e = threadIdx.x; e < 32 * HW_; e += 256) {
        int cl = e / HW_, hw = e - cl * HW_;
        s_x[hw * 33 + cl] = img[(long)b * C_ * HW_ + (long)(c0 + cl) * HW_ + hw];
    }
    int cl = threadIdx.x & 31, np = threadIdx.x >> 5;
    for (int nc = 0; nc < NCLS; nc += 16) {
        __syncthreads();
        for (int e = threadIdx.x; e < 16 * HW_; e += 256) {
            int i = e / HW_, hw = e - i * HW_;
            s_c[e] = g_logits[(b * NCLS + nc + i) * HW_ + hw];
        }
        __syncthreads();
        const float* cp0 = s_c + (2 * np) * HW_;
        const float* cp1 = cp0 + HW_;
        float acc0 = 0.f, acc1 = 0.f;
#pragma unroll 4
        for (int hw = 0; hw < HW_; hw++) {
            float x = s_x[hw * 33 + cl];
            acc0 = fmaf(x, cp0[hw], acc0);
            acc1 = fmaf(x, cp1[hw], acc1);
        }
        int n = nc + 2 * np;
        out[((long)b * NCLS + n) * C_ + c0 + cl]     = acc0;
        out[((long)b * NCLS + n + 1) * C_ + c0 + cl] = acc1;
    }
}

// ---------------- launch ----------------
extern "C" void kernel_launch(void* const* d_in, const int* in_sizes, int n_in,
                              void* d_out, int out_size) {
    (void)in_sizes; (void)n_in; (void)out_size;
    const float* img  = (const float*)d_in[0];  // [B,C,H,W]
    const float* wf   = (const float*)d_in[1];  // [N,WD]
    const float* fc1w = (const float*)d_in[2];  // [ID,C]
    const float* fc2w = (const float*)d_in[3];  // [ID,WD]
    const float* fc3w = (const float*)d_in[4];  // [ID,ID]
    // d_in[5] fc3_b, d_in[7] fc4_b: constant over softmax axis -> cancel
    const float* fc4w = (const float*)d_in[6];  // [1,ID]
    float* out = (float*)d_out;                 // [B,N,C] fp32

    k_split_a<<<dim3(64, 4), 256>>>(img);
    k_split_b<<<2048, 256>>>(fc1w);
    k_v      <<<64, 256>>>(fc3w, fc4w);
    k_wordp  <<<128, 256>>>(wf, fc2w);
    k_mma    <<<dim3(16, 7), 256>>>();
    k_logits <<<784, 256>>>();
    k_softmax<<<320, 32>>>();
    k_pool   <<<dim3(64, 4), 256>>>(img, out);
}